// round 1
// baseline (speedup 1.0000x reference)
#include <cuda_runtime.h>
#include <cstdint>

// Problem constants
#define Hc 224
#define Wc 224
#define Cc 96
#define CPc 48          // channel pairs (float2)
#define SLICES 16       // B*T
#define TAPS 49         // 7x7

// Flipped, transposed kernel: g_wT[tap*96 + c] = kernel[c*49 + (6-i)*7 + (6-j)], tap = i*7+j
__device__ float g_wT[TAPS * Cc];

__global__ void prep_kernel(const float* __restrict__ k) {
    int idx = blockIdx.x * blockDim.x + threadIdx.x;
    if (idx < TAPS * Cc) {
        int tap = idx / Cc, c = idx % Cc;
        int i = tap / 7, j = tap % 7;
        g_wT[idx] = k[c * TAPS + (6 - i) * 7 + (6 - j)];
    }
}

// Packed f32x2 FMA (Blackwell FFMA2 — only reachable via PTX)
__device__ __forceinline__ float2 ffma2(float2 a, float2 b, float2 c) {
    unsigned long long ua = *reinterpret_cast<unsigned long long*>(&a);
    unsigned long long ub = *reinterpret_cast<unsigned long long*>(&b);
    unsigned long long uc = *reinterpret_cast<unsigned long long*>(&c);
    unsigned long long ud;
    asm("fma.rn.f32x2 %0, %1, %2, %3;" : "=l"(ud) : "l"(ua), "l"(ub), "l"(uc));
    return *reinterpret_cast<float2*>(&ud);
}

// Block: blockDim = (48, 4). threadIdx.x = channel pair, threadIdx.y = h sub-band.
// Each thread computes a 2(h) x 8(w) register tile of float2 outputs for one channel pair.
// Block tile: 8(h) x 8(w) x 96(c). Grid: (W/8, H/8, 16).
__global__ __launch_bounds__(192) void conv_kernel(const float* __restrict__ x,
                                                   float* __restrict__ out) {
    __shared__ float2 wsh[TAPS * CPc];

    int tid = threadIdx.y * 48 + threadIdx.x;
    const float2* wg = reinterpret_cast<const float2*>(g_wT);
    #pragma unroll
    for (int i = tid; i < TAPS * CPc; i += 192) wsh[i] = wg[i];
    __syncthreads();

    const int cp    = threadIdx.x;
    const int slice = blockIdx.z;
    const int w0    = blockIdx.x * 8;
    const int h0    = blockIdx.y * 8 + threadIdx.y * 2;

    const float2* base = reinterpret_cast<const float2*>(x) + (size_t)slice * (Hc * Wc * CPc);

    // Wrapped column offsets (float2 units within a row), shared range across block
    int woff[14];
    #pragma unroll
    for (int j = 0; j < 14; j++) {
        int wv = w0 - 3 + j;
        if (wv < 0) wv += Wc;
        else if (wv >= Wc) wv -= Wc;
        woff[j] = wv * CPc + cp;
    }

    float2 acc0[8], acc1[8];
    #pragma unroll
    for (int i = 0; i < 8; i++) {
        acc0[i] = make_float2(0.f, 0.f);
        acc1[i] = make_float2(0.f, 0.f);
    }

    #pragma unroll
    for (int ih = 0; ih < 8; ih++) {
        int r = h0 - 3 + ih;
        if (r < 0) r += Hc;
        else if (r >= Hc) r -= Hc;
        const float2* rowp = base + (size_t)r * (Wc * CPc);

        float2 rb[14];
        #pragma unroll
        for (int j = 0; j < 14; j++) rb[j] = __ldg(&rowp[woff[j]]);

        // Output row 0 (h0): tap row i = ih, valid for ih in [0,6]
        if (ih <= 6) {
            const int dh = ih;
            #pragma unroll
            for (int dw = 0; dw < 7; dw++) {
                float2 wv = wsh[(dh * 7 + dw) * CPc + cp];
                #pragma unroll
                for (int ow = 0; ow < 8; ow++)
                    acc0[ow] = ffma2(wv, rb[ow + dw], acc0[ow]);
            }
        }
        // Output row 1 (h0+1): tap row i = ih-1, valid for ih in [1,7]
        if (ih >= 1) {
            const int dh = ih - 1;
            #pragma unroll
            for (int dw = 0; dw < 7; dw++) {
                float2 wv = wsh[(dh * 7 + dw) * CPc + cp];
                #pragma unroll
                for (int ow = 0; ow < 8; ow++)
                    acc1[ow] = ffma2(wv, rb[ow + dw], acc1[ow]);
            }
        }
    }

    float2* ob = reinterpret_cast<float2*>(out) + (size_t)slice * (Hc * Wc * CPc);
    #pragma unroll
    for (int ow = 0; ow < 8; ow++) {
        ob[(size_t)h0 * (Wc * CPc) + (w0 + ow) * CPc + cp]       = acc0[ow];
        ob[(size_t)(h0 + 1) * (Wc * CPc) + (w0 + ow) * CPc + cp] = acc1[ow];
    }
}

extern "C" void kernel_launch(void* const* d_in, const int* in_sizes, int n_in,
                              void* d_out, int out_size) {
    const float* x = (const float*)d_in[0];   // (2,8,224,224,96) fp32
    const float* k = (const float*)d_in[1];   // (96,1,7,7) fp32
    float* out = (float*)d_out;

    prep_kernel<<<(TAPS * Cc + 255) / 256, 256>>>(k);

    dim3 block(48, 4);
    dim3 grid(Wc / 8, Hc / 8, SLICES);
    conv_kernel<<<grid, block>>>(x, out);
}

// round 2
// speedup vs baseline: 2.3295x; 2.3295x over previous
#include <cuda_runtime.h>
#include <cstdint>

#define Hc 224
#define Wc 224
#define Cc 96
#define CPc 48          // channel pairs (float2 as ull)
#define TAPS 49

// Flipped kernel, transposed to [tap][c], stored as packed float2 (ull per channel pair)
__device__ unsigned long long g_wT[TAPS * CPc];

__global__ void prep_kernel(const float* __restrict__ k) {
    int idx = blockIdx.x * blockDim.x + threadIdx.x;
    if (idx < TAPS * Cc) {
        int tap = idx / Cc, c = idx % Cc;
        int i = tap / 7, j = tap % 7;
        reinterpret_cast<float*>(g_wT)[tap * Cc + c] = k[c * TAPS + (6 - i) * 7 + (6 - j)];
    }
}

// Packed dual-FMA, in-place accumulate: d.xy += a.xy * b.xy (no repacking MOVs)
__device__ __forceinline__ void ffma2(unsigned long long& d, unsigned long long a,
                                      unsigned long long b) {
    asm("fma.rn.f32x2 %0, %1, %2, %0;" : "+l"(d) : "l"(a), "l"(b));
}

// One thread: 2(h) x 8(w) output tile of one channel pair.
template <bool FAST>
__device__ __forceinline__ void conv_tile(const unsigned long long* __restrict__ base,
                                          unsigned long long* __restrict__ obase,
                                          const unsigned long long* wsh,
                                          int cp, int w0, int h0) {
    unsigned long long acc0[8], acc1[8];
    #pragma unroll
    for (int i = 0; i < 8; i++) { acc0[i] = 0ull; acc1[i] = 0ull; }

    int woff[14];
    if (!FAST) {
        #pragma unroll
        for (int j = 0; j < 14; j++) {
            int wv = w0 - 3 + j;
            if (wv < 0) wv += Wc;
            else if (wv >= Wc) wv -= Wc;
            woff[j] = wv * CPc + cp;
        }
    }
    // Interior: single base pointer, all loads are immediate-offset LDGs
    const unsigned long long* pfast =
        base + (ptrdiff_t)(h0 - 3) * (Wc * CPc) + (w0 - 3) * CPc + cp;

    #pragma unroll
    for (int ih = 0; ih < 8; ih++) {
        unsigned long long rb[14];
        if (FAST) {
            #pragma unroll
            for (int j = 0; j < 14; j++)
                rb[j] = __ldg(pfast + ih * (Wc * CPc) + j * CPc);
        } else {
            int r = h0 - 3 + ih;
            if (r < 0) r += Hc;
            else if (r >= Hc) r -= Hc;
            const unsigned long long* rowp = base + (size_t)r * (Wc * CPc);
            #pragma unroll
            for (int j = 0; j < 14; j++) rb[j] = __ldg(rowp + woff[j]);
        }
        if (ih <= 6) {            // output row h0: dh = ih
            #pragma unroll
            for (int dw = 0; dw < 7; dw++) {
                unsigned long long wv = wsh[(ih * 7 + dw) * CPc + cp];
                #pragma unroll
                for (int ow = 0; ow < 8; ow++) ffma2(acc0[ow], wv, rb[ow + dw]);
            }
        }
        if (ih >= 1) {            // output row h0+1: dh = ih-1
            #pragma unroll
            for (int dw = 0; dw < 7; dw++) {
                unsigned long long wv = wsh[((ih - 1) * 7 + dw) * CPc + cp];
                #pragma unroll
                for (int ow = 0; ow < 8; ow++) ffma2(acc1[ow], wv, rb[ow + dw]);
            }
        }
    }

    #pragma unroll
    for (int ow = 0; ow < 8; ow++) {
        obase[(size_t)h0 * (Wc * CPc) + (w0 + ow) * CPc + cp]       = acc0[ow];
        obase[(size_t)(h0 + 1) * (Wc * CPc) + (w0 + ow) * CPc + cp] = acc1[ow];
    }
}

__global__ __launch_bounds__(192, 4) void conv_kernel(const float* __restrict__ xf,
                                                      float* __restrict__ outf) {
    __shared__ unsigned long long wsh[TAPS * CPc];
    const int tid = threadIdx.x;
    #pragma unroll
    for (int i = tid; i < TAPS * CPc; i += 192) wsh[i] = g_wT[i];
    __syncthreads();

    const int cp    = tid % 48;
    const int ty    = tid / 48;
    const int slice = blockIdx.z;
    const int w0    = blockIdx.x * 8;
    const int h0    = blockIdx.y * 8 + ty * 2;

    const unsigned long long* base =
        reinterpret_cast<const unsigned long long*>(xf) + (size_t)slice * (Hc * Wc * CPc);
    unsigned long long* obase =
        reinterpret_cast<unsigned long long*>(outf) + (size_t)slice * (Hc * Wc * CPc);

    const bool fast = (blockIdx.x >= 1) & (blockIdx.x <= 26) &
                      (blockIdx.y >= 1) & (blockIdx.y <= 26);
    if (fast) conv_tile<true>(base, obase, wsh, cp, w0, h0);
    else      conv_tile<false>(base, obase, wsh, cp, w0, h0);
}

extern "C" void kernel_launch(void* const* d_in, const int* in_sizes, int n_in,
                              void* d_out, int out_size) {
    const float* x = (const float*)d_in[0];   // (2,8,224,224,96) fp32
    const float* k = (const float*)d_in[1];   // (96,1,7,7) fp32
    float* out = (float*)d_out;

    prep_kernel<<<(TAPS * Cc + 255) / 256, 256>>>(k);

    dim3 block(192);
    dim3 grid(Wc / 8, Hc / 8, 16);
    conv_kernel<<<grid, block>>>(x, out);
}